// round 17
// baseline (speedup 1.0000x reference)
#include <cuda_runtime.h>
#include <math.h>

// ---------------------------------------------------------------------------
// expression[c,g] = bias1[gene_ix[g]] + sum_{frags in bucket c*gene_n+g}
//                   dot(sin(coords[f,:,None]*freq+shift).reshape(40), w)
// Per-fragment scalar g0(x)+g1(y): two fixed 1-D LUTs + lerp (err ~3e-6).
// R17 = R5 pipeline lifted to bucket-PAIR granularity: run combine + scan on
// p = bucket>>1 with float2 {even,odd} values; every flush is ONE
// red.global.add.v2.f32 (8B) -> RED lane count drops ~40% (the validated
// per-SM LSU model says REDs are 60% of the kernel).
// ---------------------------------------------------------------------------

#define TAB      256
#define T_LO     (-9.0f)
#define T_HI     ( 9.0f)
#define FULL     0xffffffffu
#define NBLK     888              // 6 blocks/SM x 148 SMs = one wave

__device__ float2 g_tbl[2][TAB];  // (value, slope-to-next)

// ---------------------------------------------------------------------------
// prep: first TBL_BLOCKS blocks build the LUT; remaining init out = bias.
// ---------------------------------------------------------------------------
#define TBL_POINTS  (2 * TAB)
#define TBL_BLOCKS  ((TBL_POINTS * 32 + 255) / 256)
#define INIT_ROWS   8

__global__ void prep_kernel(const float* __restrict__ freqs,
                            const float* __restrict__ shifts,
                            const float* __restrict__ w,
                            const float* __restrict__ bias,
                            const int*   __restrict__ gene_ix,
                            float*       __restrict__ out,
                            int gene_n, int total)
{
    if (blockIdx.x < TBL_BLOCKS) {
        int gw   = blockIdx.x * (blockDim.x >> 5) + (threadIdx.x >> 5);
        int lane = threadIdx.x & 31;
        if (gw < TBL_POINTS) {
            int which = gw / TAB;
            int k     = gw % TAB;
            const float step = (T_HI - T_LO) / (float)TAB;
            float x0 = T_LO + (float)k * step;
            float x1 = x0 + step;
            float v0 = 0.f, v1 = 0.f;
            if (lane < 20) {
                float f = freqs[lane], s = shifts[lane], c = w[which * 20 + lane];
                v0 = c * sinf(fmaf(x0, f, s));
                v1 = c * sinf(fmaf(x1, f, s));
            }
            #pragma unroll
            for (int off = 16; off; off >>= 1) {
                v0 += __shfl_down_sync(FULL, v0, off);
                v1 += __shfl_down_sync(FULL, v1, off);
            }
            if (lane == 0) g_tbl[which][k] = make_float2(v0, v1 - v0);
        }
        return;
    }

    int ib = blockIdx.x - TBL_BLOCKS;

    if ((gene_n & 3) == 0 && gene_n <= 4096 && total % gene_n == 0) {
        __shared__ float pb[4096];
        for (int g = threadIdx.x; g < gene_n; g += blockDim.x)
            pb[g] = __ldg(&bias[__ldg(&gene_ix[g])]);
        __syncthreads();

        const float4* pb4 = reinterpret_cast<const float4*>(pb);
        float4*       o4  = reinterpret_cast<float4*>(out);
        int row_q  = gene_n >> 2;
        int rows   = total / gene_n;
        int r0     = ib * INIT_ROWS;
        int nq     = min(INIT_ROWS, rows - r0) * row_q;
        if (nq <= 0) return;
        long base4 = (long)r0 * row_q;
        for (int t = threadIdx.x; t < nq; t += blockDim.x)
            o4[base4 + t] = pb4[t % row_q];
    } else {
        for (long i = (long)ib * blockDim.x * INIT_ROWS * 4 + threadIdx.x;
             i < (long)total && i < (long)(ib + 1) * blockDim.x * INIT_ROWS * 4;
             i += blockDim.x)
            out[i] = __ldg(&bias[__ldg(&gene_ix[(int)(i % gene_n)])]);
    }
}

// ---------------------------------------------------------------------------
__device__ __forceinline__ float lerp1(const float2* __restrict__ s, float x)
{
    const float scale = (float)TAB / (T_HI - T_LO);
    const float offs  = -T_LO * scale;
    const float hi    = (float)TAB - 0.001f;
    float u = fminf(fmaxf(fmaf(x, scale, offs), 0.f), hi);
    int   k = (int)u;
    float fr = u - (float)k;
    float2 t = s[k];
    return fmaf(fr, t.y, t.x);
}

__device__ __forceinline__ float2 f2add(float2 a, float2 b)
{ return make_float2(a.x + b.x, a.y + b.y); }

__device__ __forceinline__ float2 f2sel(bool c, float2 a)   // c ? a : 0
{ return make_float2(c ? a.x : 0.f, c ? a.y : 0.f); }

// One 8B vector RED covering buckets (2p, 2p+1).
__device__ __forceinline__ void red_v2(float* __restrict__ out, int p, float2 v)
{
    asm volatile("red.global.add.v2.f32 [%0], {%1, %2};"
                 :: "l"(out + 2 * (long)p), "f"(v.x), "f"(v.y) : "memory");
}

// Scalar-safe fallback flush (odd out_size).
__device__ __forceinline__ void red_v2_safe(float* __restrict__ out, int p,
                                            float2 v, int total)
{
    atomicAdd(out + 2 * (long)p, v.x);
    if (2 * p + 1 < total) atomicAdd(out + 2 * (long)p + 1, v.y);
}

// ---------------------------------------------------------------------------
template <bool VEC>
__global__ void __launch_bounds__(256, 6)
frag_kernel(const float4* __restrict__ coords2,   // 2 frags per element
            const int4*   __restrict__ ix4,       // 4 bucket ids per element
            const float*  __restrict__ coords_raw,
            const int*    __restrict__ ix_raw,
            float*        __restrict__ out,
            int nquads, int F, int total)
{
    __shared__ float2 s0[TAB];
    __shared__ float2 s1[TAB];
    {
        const float2* src = &g_tbl[0][0];
        for (int i = threadIdx.x; i < 2 * TAB; i += blockDim.x) {
            float2 v = src[i];
            if (i < TAB) s0[i] = v; else s1[i - TAB] = v;
        }
    }
    __syncthreads();

    // Leftover fragments (F % 4): one thread, scalar REDs.
    if (blockIdx.x == 0 && threadIdx.x == 0) {
        for (int f = 4 * nquads; f < F; ++f) {
            float x = coords_raw[2 * f], y = coords_raw[2 * f + 1];
            atomicAdd(out + ix_raw[f], lerp1(s0, x) + lerp1(s1, y));
        }
    }

    int lane   = threadIdx.x & 31;
    int gwarp  = (blockIdx.x * blockDim.x + threadIdx.x) >> 5;
    int nwarps = (NBLK * 256) >> 5;

    for (long qbase = (long)gwarp * 32; qbase < (long)nquads;
         qbase += (long)nwarps * 32) {
        long q     = qbase + lane;
        bool valid = q < (long)nquads;

        float4 cA = make_float4(0,0,0,0), cB = make_float4(0,0,0,0);
        int4   bb = make_int4(-1,-1,-1,-1);
        if (valid) {
            cA = __ldcs(&coords2[2 * q]);
            cB = __ldcs(&coords2[2 * q + 1]);
            bb = __ldcs(&ix4[q]);
        }

        float v0 = lerp1(s0, cA.x) + lerp1(s1, cA.y);
        float v1 = lerp1(s0, cA.z) + lerp1(s1, cA.w);
        float v2 = lerp1(s0, cB.x) + lerp1(s1, cB.y);
        float v3 = lerp1(s0, cB.z) + lerp1(s1, cB.w);

        // Pair ids + parity-placed float2 values.
        int p0 = bb.x >> 1, p1 = bb.y >> 1, p2 = bb.z >> 1, p3 = bb.w >> 1;
        float2 f0 = (bb.x & 1) ? make_float2(0.f, v0) : make_float2(v0, 0.f);
        float2 f1 = (bb.y & 1) ? make_float2(0.f, v1) : make_float2(v1, 0.f);
        float2 f2 = (bb.z & 1) ? make_float2(0.f, v2) : make_float2(v2, 0.f);
        float2 f3 = (bb.w & 1) ? make_float2(0.f, v3) : make_float2(v3, 0.f);

        // Branchless cumulative run chain over the 4 sorted PAIR ids.
        bool e01 = (p0 == p1), e12 = (p1 == p2), e23 = (p2 == p3);
        float2 c0 = f0;
        float2 c1 = f2add(f1, f2sel(e01, c0));
        float2 c2 = f2add(f2, f2sel(e12, c1));
        float2 c3 = f2add(f3, f2sel(e23, c2));
        bool   same = e01 && e12 && e23;
        float2 hsum = !e01 ? c0 : (!e12 ? c1 : c2);

        // Cross-lane: tail pair-run (pair p3, sum c3) segmented scan.
        int  st_prev = __shfl_up_sync(FULL, p3, 1);
        bool cont    = (lane > 0) && same && (st_prev == p3);

        unsigned hb    = __ballot_sync(FULL, !cont);
        unsigned below = hb & (0xffffffffu >> (31 - lane));
        int seg = 31 - __clz(below);                 // bit 0 always set

        float2 S = c3;
        #pragma unroll
        for (int off = 1; off < 32; off <<= 1) {
            float nx = __shfl_up_sync(FULL, S.x, off);
            float ny = __shfl_up_sync(FULL, S.y, off);
            if (lane - off >= seg) { S.x += nx; S.y += ny; }
        }

        float2 Sprev;
        Sprev.x = __shfl_up_sync(FULL, S.x, 1);
        Sprev.y = __shfl_up_sync(FULL, S.y, 1);
        int  np0 = __shfl_down_sync(FULL, p0, 1);
        bool consumed = (lane < 31) && (np0 == p3);

        bool f_int1 = valid && !e12 && !e01;
        bool f_int2 = valid && !e23 && !(e01 && e12);
        bool f_head = valid && !same;
        bool f_tail = valid && !consumed;
        float2 hv = f2add(hsum, f2sel(lane > 0 && st_prev == p0, Sprev));

        if (VEC) {
            if (f_int1) red_v2(out, p1, c1);
            if (f_int2) red_v2(out, p2, c2);
            if (f_head) red_v2(out, p0, hv);
            if (f_tail) red_v2(out, p3, S);
        } else {
            if (f_int1) red_v2_safe(out, p1, c1, total);
            if (f_int2) red_v2_safe(out, p2, c2, total);
            if (f_head) red_v2_safe(out, p0, hv, total);
            if (f_tail) red_v2_safe(out, p3, S, total);
        }
    }
}

// ---------------------------------------------------------------------------
extern "C" void kernel_launch(void* const* d_in, const int* in_sizes, int n_in,
                              void* d_out, int out_size)
{
    // 0 coords, 1 cellxgene_ix, 2 cell_n, 3 gene_n, 4 gene_ix,
    // 5 frequencies, 6 shifts, 7 weight1, 8 bias1
    int off = (n_in >= 9) ? 0 : -2;

    const float* coords  = (const float*)d_in[0];
    const int*   ix      = (const int*)  d_in[1];
    const int*   gene_ix = (const int*)  d_in[4 + off];
    const float* freqs   = (const float*)d_in[5 + off];
    const float* shifts  = (const float*)d_in[6 + off];
    const float* w       = (const float*)d_in[7 + off];
    const float* bias    = (const float*)d_in[8 + off];

    int F      = in_sizes[0] / 2;
    int gene_n = in_sizes[4 + off];
    float* out = (float*)d_out;

    int init_blocks;
    if ((gene_n & 3) == 0 && gene_n <= 4096 && out_size % gene_n == 0) {
        int rows = out_size / gene_n;
        init_blocks = (rows + INIT_ROWS - 1) / INIT_ROWS;
    } else {
        init_blocks = (out_size + 256 * INIT_ROWS * 4 - 1) / (256 * INIT_ROWS * 4);
    }
    prep_kernel<<<TBL_BLOCKS + init_blocks, 256>>>(freqs, shifts, w, bias,
                                                   gene_ix, out, gene_n, out_size);

    int nquads = F / 4;
    if ((out_size & 1) == 0)
        frag_kernel<true><<<NBLK, 256>>>((const float4*)coords, (const int4*)ix,
                                         coords, ix, out, nquads, F, out_size);
    else
        frag_kernel<false><<<NBLK, 256>>>((const float4*)coords, (const int4*)ix,
                                          coords, ix, out, nquads, F, out_size);
}